// round 11
// baseline (speedup 1.0000x reference)
#include <cuda_runtime.h>
#include <cstdint>

// GeneralizedGraphDiffusion: out = prelu((sum_k theta_k*T_k * a) @ x) @ W^T + b
// N=8192, D=128, K=4.
// R11: R10 pipeline (cp.async 3-stage ring, 1 barrier/tile, build(t+1)||mma(t))
// with TPB 256->512: 16 warps, warp tile 16x32, half the per-warp chain length.

#define NN 8192
#define DDIM 128
#define BM 64
#define BK 32
#define NT 256
#define TPB 512

// smem float offsets
#define TSTG 10240              // per stage: T 4*2048 + a 2048
#define XRAW 30720              // 3 * TSTG
#define XSTG 4352               // [32][136]
#define XSTR 136
#define AOFF 43776              // XRAW + 3*XSTG ; A double buffer 2*2304
#define SMEM_WORDS 48384        // 193536 bytes
#define HS_STRIDE 132

extern __shared__ float sm[];

__device__ __forceinline__ uint32_t tf32r(float f) {
    uint32_t r;
    asm("cvt.rna.tf32.f32 %0, %1;" : "=r"(r) : "f"(f));
    return r;
}
__device__ __forceinline__ void mma8(float* c, uint32_t a0, uint32_t a1,
                                     uint32_t a2, uint32_t a3,
                                     uint32_t b0, uint32_t b1) {
    asm volatile(
        "mma.sync.aligned.m16n8k8.row.col.f32.tf32.tf32.f32 "
        "{%0,%1,%2,%3}, {%4,%5,%6,%7}, {%8,%9}, {%0,%1,%2,%3};"
        : "+f"(c[0]), "+f"(c[1]), "+f"(c[2]), "+f"(c[3])
        : "r"(a0), "r"(a1), "r"(a2), "r"(a3), "r"(b0), "r"(b1));
}
__device__ __forceinline__ void cpa16(uint32_t dst, const float* src) {
    asm volatile("cp.async.cg.shared.global [%0], [%1], 16;" :: "r"(dst), "l"(src));
}
#define CP_COMMIT() asm volatile("cp.async.commit_group;" ::: "memory")
#define CP_WAIT1()  asm volatile("cp.async.wait_group 1;" ::: "memory")
#define STS128(ad, x, y, z, w) \
    asm volatile("st.shared.v4.b32 [%0], {%1,%2,%3,%4};" :: \
        "r"(ad), "r"(x), "r"(y), "r"(z), "r"(w) : "memory")

__global__ __launch_bounds__(TPB, 1)
void ggd_kernel(const float* __restrict__ theta, const float* __restrict__ T,
                const float* __restrict__ x, const float* __restrict__ a,
                const float* __restrict__ alpha, const float* __restrict__ W,
                const float* __restrict__ bias, float* __restrict__ out) {
    const int tid = threadIdx.x;
    const int lane = tid & 31, wid = tid >> 5;
    const int g = lane >> 2, tig = lane & 3;
    const int wr = wid & 3, wc = wid >> 2;   // 16-row x 32-col warp tile
    const int i0 = blockIdx.x * BM;
    const size_t slice = (size_t)NN * NN;

    uint32_t sbase;
    asm("{ .reg .u64 t; cvta.to.shared.u64 t, %1; cvt.u32.u64 %0, t; }"
        : "=r"(sbase) : "l"(sm));

    // ---- cp.async source/dst precompute (512 threads) ----
    // T: 2048 chunks -> 4/thread; a: 512 -> 1/thread; x: 1024 -> 2/thread
    const float* srcT[4]; uint32_t dstT[4];
#pragma unroll
    for (int q = 0; q < 4; q++) {
        int c = tid + q * 512;
        int k = c >> 9, rem = c & 511, r = rem >> 3, cc = (rem & 7) * 4;
        srcT[q] = T + (size_t)k * slice + (size_t)(i0 + r) * NN + cc;
        dstT[q] = (uint32_t)c * 16;
    }
    const float* srcA0 = a + (size_t)(i0 + (tid >> 3)) * NN + (tid & 7) * 4;
    const uint32_t dstA0 = 8192 * 4 + (uint32_t)tid * 16;
    const float* srcX[2]; uint32_t dstX[2];
#pragma unroll
    for (int q = 0; q < 2; q++) {
        int c = tid + q * 512;
        int row = c >> 5, cc = (c & 31) * 4;
        srcX[q] = x + (size_t)row * DDIM + cc;
        dstX[q] = (uint32_t)(row * XSTR + cc) * 4;
    }

#define ISSUE(J0, STG) do {                                                    \
    uint32_t _tb = sbase + (uint32_t)((STG) * TSTG) * 4;                       \
    uint32_t _xb = sbase + (uint32_t)(XRAW + (STG) * XSTG) * 4;                \
    _Pragma("unroll") for (int _q = 0; _q < 4; _q++)                           \
        cpa16(_tb + dstT[_q], srcT[_q] + (J0));                                \
    cpa16(_tb + dstA0, srcA0 + (J0));                                          \
    _Pragma("unroll") for (int _q = 0; _q < 2; _q++)                           \
        cpa16(_xb + dstX[_q], srcX[_q] + (size_t)(J0) * DDIM);                 \
} while (0)

    const float th0 = __ldg(theta), th1 = __ldg(theta + 1),
                th2 = __ldg(theta + 2), th3 = __ldg(theta + 3);

// build q tile + cvt x for TILE from its raw slot into A[TILE&1] / X slot
#define BUILD(TILE) do {                                                       \
    int _s = (TILE) % 3;                                                       \
    const float* _traw = sm + _s * TSTG;                                       \
    const float* _araw = _traw + 8192;                                         \
    float* _Xb = sm + XRAW + _s * XSTG;                                        \
    uint32_t _Abad = sbase + (uint32_t)(AOFF + ((TILE) & 1) * 2304) * 4;       \
    {                                                                          \
        int _row = tid >> 3, _c4 = (tid & 7) * 4;                              \
        float4 _t0 = *(const float4*)(_traw + _row * 32 + _c4);                \
        float4 _t1 = *(const float4*)(_traw + 2048 + _row * 32 + _c4);         \
        float4 _t2 = *(const float4*)(_traw + 4096 + _row * 32 + _c4);         \
        float4 _t3 = *(const float4*)(_traw + 6144 + _row * 32 + _c4);         \
        float4 _av = *(const float4*)(_araw + _row * 32 + _c4);                \
        uint32_t _qx = tf32r((th0*_t0.x + th1*_t1.x + th2*_t2.x + th3*_t3.x) * _av.x); \
        uint32_t _qy = tf32r((th0*_t0.y + th1*_t1.y + th2*_t2.y + th3*_t3.y) * _av.y); \
        uint32_t _qz = tf32r((th0*_t0.z + th1*_t1.z + th2*_t2.z + th3*_t3.z) * _av.z); \
        uint32_t _qw = tf32r((th0*_t0.w + th1*_t1.w + th2*_t2.w + th3*_t3.w) * _av.w); \
        STS128(_Abad + (uint32_t)(_row * 36 + _c4) * 4, _qx, _qy, _qz, _qw);   \
    }                                                                          \
    _Pragma("unroll") for (int _qq = 0; _qq < 2; _qq++) {                      \
        int _idx = tid + _qq * 512;                                            \
        float* _p = _Xb + (_idx >> 5) * XSTR + (_idx & 31) * 4;                \
        float4 _v = *(const float4*)_p;                                        \
        uint32_t _pa;                                                          \
        asm("{ .reg .u64 t; cvta.to.shared.u64 t, %1; cvt.u32.u64 %0, t; }"    \
            : "=r"(_pa) : "l"(_p));                                            \
        STS128(_pa, tf32r(_v.x), tf32r(_v.y), tf32r(_v.z), tf32r(_v.w));       \
    }                                                                          \
} while (0)

    float acc[4][4];
#pragma unroll
    for (int nf = 0; nf < 4; nf++)
#pragma unroll
        for (int e = 0; e < 4; e++) acc[nf][e] = 0.f;

    // prologue: raw 0,1 in flight; build tile 0
    ISSUE(0, 0);  CP_COMMIT();
    ISSUE(BK, 1); CP_COMMIT();
    CP_WAIT1();
    __syncthreads();
    BUILD(0);

    for (int t = 0; t < NT; t++) {
        __syncthreads();   // build(t) visible; frees raw slot (t-1)%3 and A[(t+1)&1]
        if (t + 2 < NT) {
            int stg = t + 2 - ((t + 2) / 3) * 3;
            ISSUE((t + 2) * BK, stg);
        }
        CP_COMMIT();
        if (t + 1 < NT) {
            CP_WAIT1();
            BUILD(t + 1);
        }

        // ---- mma(t): A[t&1], X slot t%3 ----
        const uint32_t* As = (const uint32_t*)(sm + AOFF + (t & 1) * 2304);
        const uint32_t* Xs = (const uint32_t*)(sm + XRAW + (t % 3) * XSTG);
#pragma unroll
        for (int ks = 0; ks < 4; ks++) {
            const uint32_t* ap = As + (wr*16 + g) * 36 + ks*8 + tig;
            uint32_t a0 = ap[0];
            uint32_t a1 = ap[8 * 36];
            uint32_t a2 = ap[4];
            uint32_t a3 = ap[8 * 36 + 4];
#pragma unroll
            for (int nfl = 0; nfl < 4; nfl++) {
                const int n = (wc*4 + nfl)*8 + g;
                uint32_t b0 = Xs[(ks*8 + tig)     * XSTR + n];
                uint32_t b1 = Xs[(ks*8 + tig + 4) * XSTR + n];
                mma8(acc[nfl], a0, a1, a2, a3, b0, b1);
            }
        }
    }

    // ---- epilogue: acc -> hs, prelu + projection ----
    __syncthreads();
    float* hs = sm;   // [64][HS_STRIDE]
#pragma unroll
    for (int nfl = 0; nfl < 4; nfl++) {
        const int col = (wc*4 + nfl)*8 + tig*2;
        const int r0 = wr*16 + g;
        *(float2*)(hs + r0 * HS_STRIDE + col) = make_float2(acc[nfl][0], acc[nfl][1]);
        *(float2*)(hs + (r0 + 8) * HS_STRIDE + col) = make_float2(acc[nfl][2], acc[nfl][3]);
    }
    __syncthreads();

    const int tx = tid & 15, ty = tid >> 4;   // ty 0..31, 2 rows each
    const int tx8 = tx * 8, ty2 = ty * 2;
    float oa[2][8];
#pragma unroll
    for (int m = 0; m < 2; m++)
#pragma unroll
        for (int u = 0; u < 8; u++) oa[m][u] = 0.f;

    for (int c4 = 0; c4 < 32; c4++) {
        float4 al = __ldg((const float4*)(alpha + c4 * 4));
        float4 wv[8];
#pragma unroll
        for (int u = 0; u < 8; u++)
            wv[u] = __ldg((const float4*)(W + (size_t)(tx8 + u) * DDIM + c4 * 4));
#pragma unroll
        for (int m = 0; m < 2; m++) {
            float4 hv = *(const float4*)(hs + (ty2 + m) * HS_STRIDE + c4 * 4);
            hv.x = hv.x > 0.f ? hv.x : al.x * hv.x;
            hv.y = hv.y > 0.f ? hv.y : al.y * hv.y;
            hv.z = hv.z > 0.f ? hv.z : al.z * hv.z;
            hv.w = hv.w > 0.f ? hv.w : al.w * hv.w;
#pragma unroll
            for (int u = 0; u < 8; u++)
                oa[m][u] += hv.x * wv[u].x + hv.y * wv[u].y +
                            hv.z * wv[u].z + hv.w * wv[u].w;
        }
    }
    float4 b0 = __ldg((const float4*)(bias + tx8));
    float4 b1 = __ldg((const float4*)(bias + tx8 + 4));
#pragma unroll
    for (int m = 0; m < 2; m++) {
        size_t go = (size_t)(i0 + ty2 + m) * DDIM;
        *(float4*)(out + go + tx8) =
            make_float4(oa[m][0] + b0.x, oa[m][1] + b0.y,
                        oa[m][2] + b0.z, oa[m][3] + b0.w);
        *(float4*)(out + go + tx8 + 4) =
            make_float4(oa[m][4] + b1.x, oa[m][5] + b1.y,
                        oa[m][6] + b1.z, oa[m][7] + b1.w);
    }
}

extern "C" void kernel_launch(void* const* d_in, const int* in_sizes, int n_in,
                              void* d_out, int out_size) {
    const float* theta = (const float*)d_in[0];
    const float* T     = (const float*)d_in[1];
    const float* x     = (const float*)d_in[2];
    const float* a     = (const float*)d_in[3];
    const float* alpha = (const float*)d_in[4];
    const float* W     = (const float*)d_in[5];
    const float* bias  = (const float*)d_in[6];
    (void)in_sizes; (void)n_in; (void)out_size;

    cudaFuncSetAttribute(ggd_kernel, cudaFuncAttributeMaxDynamicSharedMemorySize,
                         SMEM_WORDS * 4);
    ggd_kernel<<<NN / BM, TPB, SMEM_WORDS * 4>>>(theta, T, x, a, alpha, W, bias,
                                                 (float*)d_out);
}

// round 12
// speedup vs baseline: 1.0475x; 1.0475x over previous
#include <cuda_runtime.h>
#include <cstdint>

// GeneralizedGraphDiffusion: out = prelu((sum_k theta_k*T_k * a) @ x) @ W^T + b
// N=8192, D=128, K=4.
// R12: 16 warps (R11 partition) + register staging (R6 style, no cp.async ring,
// no raw smem roundtrip). One barrier per tile. mma.sync tf32. grid 128, BM 64.

#define NN 8192
#define DDIM 128
#define BM 64
#define BK 32
#define NT 256
#define TPB 512

// smem float offsets
#define XSTG 4352               // [32][136]
#define XSTR 136
#define A0O 0                   // A double buffer 2*2304
#define X0O 4608                // X double buffer 2*4352
#define SMEM_WORDS 13312        // 53248 bytes
#define HS_STRIDE 132

extern __shared__ float sm[];

__device__ __forceinline__ uint32_t tf32r(float f) {
    uint32_t r;
    asm("cvt.rna.tf32.f32 %0, %1;" : "=r"(r) : "f"(f));
    return r;
}
__device__ __forceinline__ void mma8(float* c, uint32_t a0, uint32_t a1,
                                     uint32_t a2, uint32_t a3,
                                     uint32_t b0, uint32_t b1) {
    asm volatile(
        "mma.sync.aligned.m16n8k8.row.col.f32.tf32.tf32.f32 "
        "{%0,%1,%2,%3}, {%4,%5,%6,%7}, {%8,%9}, {%0,%1,%2,%3};"
        : "+f"(c[0]), "+f"(c[1]), "+f"(c[2]), "+f"(c[3])
        : "r"(a0), "r"(a1), "r"(a2), "r"(a3), "r"(b0), "r"(b1));
}
#define STS128(ad, x, y, z, w) \
    asm volatile("st.shared.v4.b32 [%0], {%1,%2,%3,%4};" :: \
        "r"(ad), "r"(x), "r"(y), "r"(z), "r"(w) : "memory")

__global__ __launch_bounds__(TPB, 1)
void ggd_kernel(const float* __restrict__ theta, const float* __restrict__ T,
                const float* __restrict__ x, const float* __restrict__ a,
                const float* __restrict__ alpha, const float* __restrict__ W,
                const float* __restrict__ bias, float* __restrict__ out) {
    const int tid = threadIdx.x;
    const int lane = tid & 31, wid = tid >> 5;
    const int g = lane >> 2, tig = lane & 3;
    const int wr = wid & 3, wc = wid >> 2;   // 16-row x 32-col warp tile
    const int i0 = blockIdx.x * BM;
    const size_t slice = (size_t)NN * NN;

    uint32_t sbase;
    asm("{ .reg .u64 t; cvta.to.shared.u64 t, %1; cvt.u32.u64 %0, t; }"
        : "=r"(sbase) : "l"(sm));

    // ---- staging assignment ----
    // q: 512 quads (64 rows x 8 col-quads), 1/thread
    const int qrow = tid >> 3, qc4 = (tid & 7) * 4;
    const size_t rbA = (size_t)(i0 + qrow) * NN + qc4;
    const uint32_t stA = sbase + (uint32_t)(qrow * 36 + qc4) * 4;
    // x: 1024 float4 (32 rows x 32 col-quads), 2/thread
    const int xr0 = tid >> 5,          xc0 = (tid & 31) * 4;
    const int xr1 = (tid + 512) >> 5,  xc1 = ((tid + 512) & 31) * 4;
    const uint32_t stX0 = sbase + (uint32_t)(X0O + xr0 * XSTR + xc0) * 4;
    const uint32_t stX1 = sbase + (uint32_t)(X0O + xr1 * XSTR + xc1) * 4;

    const float th0 = __ldg(theta), th1 = __ldg(theta + 1),
                th2 = __ldg(theta + 2), th3 = __ldg(theta + 3);

    float4 pT0, pT1, pT2, pT3, pa, px0, px1;

#define LOADR(J0) do {                                                         \
    size_t _o = rbA + (size_t)(J0);                                            \
    pT0 = *(const float4*)(T + _o);                                            \
    pT1 = *(const float4*)(T + slice + _o);                                    \
    pT2 = *(const float4*)(T + 2 * slice + _o);                                \
    pT3 = *(const float4*)(T + 3 * slice + _o);                                \
    pa  = *(const float4*)(a + _o);                                            \
    px0 = *(const float4*)(x + (size_t)((J0) + xr0) * DDIM + xc0);             \
    px1 = *(const float4*)(x + (size_t)((J0) + xr1) * DDIM + xc1);             \
} while (0)

#define STORE(BUFSEL) do {                                                     \
    uint32_t _ab = stA + (uint32_t)(BUFSEL) * 2304 * 4;                        \
    uint32_t _qx = tf32r((th0*pT0.x + th1*pT1.x + th2*pT2.x + th3*pT3.x) * pa.x); \
    uint32_t _qy = tf32r((th0*pT0.y + th1*pT1.y + th2*pT2.y + th3*pT3.y) * pa.y); \
    uint32_t _qz = tf32r((th0*pT0.z + th1*pT1.z + th2*pT2.z + th3*pT3.z) * pa.z); \
    uint32_t _qw = tf32r((th0*pT0.w + th1*pT1.w + th2*pT2.w + th3*pT3.w) * pa.w); \
    STS128(_ab, _qx, _qy, _qz, _qw);                                           \
    uint32_t _xo = (uint32_t)(BUFSEL) * XSTG * 4;                              \
    STS128(stX0 + _xo, tf32r(px0.x), tf32r(px0.y), tf32r(px0.z), tf32r(px0.w)); \
    STS128(stX1 + _xo, tf32r(px1.x), tf32r(px1.y), tf32r(px1.z), tf32r(px1.w)); \
} while (0)

    float acc[4][4];
#pragma unroll
    for (int nf = 0; nf < 4; nf++)
#pragma unroll
        for (int e = 0; e < 4; e++) acc[nf][e] = 0.f;

    LOADR(0);
    for (int t = 0; t < NT; t++) {
        const int b = t & 1;
        STORE(b);              // consumes regs loaded last iter; writes buf b
        __syncthreads();       // buf b visible; all warps past mma(t-1) (buf b^1)
        if (t + 1 < NT) LOADR((t + 1) * BK);   // lands during mma(t)

        // ---- mma(t): A[b], X[b] ----
        const uint32_t* As = (const uint32_t*)(sm + b * 2304);
        const uint32_t* Xs = (const uint32_t*)(sm + X0O + b * XSTG);
#pragma unroll
        for (int ks = 0; ks < 4; ks++) {
            const uint32_t* ap = As + (wr*16 + g) * 36 + ks*8 + tig;
            uint32_t a0 = ap[0];
            uint32_t a1 = ap[8 * 36];
            uint32_t a2 = ap[4];
            uint32_t a3 = ap[8 * 36 + 4];
#pragma unroll
            for (int nfl = 0; nfl < 4; nfl++) {
                const int n = (wc*4 + nfl)*8 + g;
                uint32_t b0 = Xs[(ks*8 + tig)     * XSTR + n];
                uint32_t b1 = Xs[(ks*8 + tig + 4) * XSTR + n];
                mma8(acc[nfl], a0, a1, a2, a3, b0, b1);
            }
        }
    }

    // ---- epilogue: acc -> hs, prelu + projection ----
    __syncthreads();
    float* hs = sm;   // [64][HS_STRIDE] = 8448 words
#pragma unroll
    for (int nfl = 0; nfl < 4; nfl++) {
        const int col = (wc*4 + nfl)*8 + tig*2;
        const int r0 = wr*16 + g;
        *(float2*)(hs + r0 * HS_STRIDE + col) = make_float2(acc[nfl][0], acc[nfl][1]);
        *(float2*)(hs + (r0 + 8) * HS_STRIDE + col) = make_float2(acc[nfl][2], acc[nfl][3]);
    }
    __syncthreads();

    const int tx = tid & 15, ty = tid >> 4;   // ty 0..31, 2 rows each
    const int tx8 = tx * 8, ty2 = ty * 2;
    float oa[2][8];
#pragma unroll
    for (int m = 0; m < 2; m++)
#pragma unroll
        for (int u = 0; u < 8; u++) oa[m][u] = 0.f;

    for (int c4 = 0; c4 < 32; c4++) {
        float4 al = __ldg((const float4*)(alpha + c4 * 4));
        float4 wv[8];
#pragma unroll
        for (int u = 0; u < 8; u++)
            wv[u] = __ldg((const float4*)(W + (size_t)(tx8 + u) * DDIM + c4 * 4));
#pragma unroll
        for (int m = 0; m < 2; m++) {
            float4 hv = *(const float4*)(hs + (ty2 + m) * HS_STRIDE + c4 * 4);
            hv.x = hv.x > 0.f ? hv.x : al.x * hv.x;
            hv.y = hv.y > 0.f ? hv.y : al.y * hv.y;
            hv.z = hv.z > 0.f ? hv.z : al.z * hv.z;
            hv.w = hv.w > 0.f ? hv.w : al.w * hv.w;
#pragma unroll
            for (int u = 0; u < 8; u++)
                oa[m][u] += hv.x * wv[u].x + hv.y * wv[u].y +
                            hv.z * wv[u].z + hv.w * wv[u].w;
        }
    }
    float4 b0 = __ldg((const float4*)(bias + tx8));
    float4 b1 = __ldg((const float4*)(bias + tx8 + 4));
#pragma unroll
    for (int m = 0; m < 2; m++) {
        size_t go = (size_t)(i0 + ty2 + m) * DDIM;
        *(float4*)(out + go + tx8) =
            make_float4(oa[m][0] + b0.x, oa[m][1] + b0.y,
                        oa[m][2] + b0.z, oa[m][3] + b0.w);
        *(float4*)(out + go + tx8 + 4) =
            make_float4(oa[m][4] + b1.x, oa[m][5] + b1.y,
                        oa[m][6] + b1.z, oa[m][7] + b1.w);
    }
}

extern "C" void kernel_launch(void* const* d_in, const int* in_sizes, int n_in,
                              void* d_out, int out_size) {
    const float* theta = (const float*)d_in[0];
    const float* T     = (const float*)d_in[1];
    const float* x     = (const float*)d_in[2];
    const float* a     = (const float*)d_in[3];
    const float* alpha = (const float*)d_in[4];
    const float* W     = (const float*)d_in[5];
    const float* bias  = (const float*)d_in[6];
    (void)in_sizes; (void)n_in; (void)out_size;

    cudaFuncSetAttribute(ggd_kernel, cudaFuncAttributeMaxDynamicSharedMemorySize,
                         SMEM_WORDS * 4);
    ggd_kernel<<<NN / BM, TPB, SMEM_WORDS * 4>>>(theta, T, x, a, alpha, W, bias,
                                                 (float*)d_out);
}

// round 13
// speedup vs baseline: 1.0655x; 1.0172x over previous
#include <cuda_runtime.h>
#include <cstdint>

// GeneralizedGraphDiffusion: out = prelu((sum_k theta_k*T_k * a) @ x) @ W^T + b
// N=8192, D=128, K=4.
// R13: R9 (cp.async 3-stage ring, 8 warps, mma.sync tf32) with BM 64->56,
// grid 147 -> all 148 SMs covered. Rows 56..63 are clamped duplicates,
// computed but never stored.

#define NN 8192
#define DDIM 128
#define BM 56
#define BK 32
#define NT 256
#define TPB 256

// smem float offsets
#define TSTG 10240              // per stage: T 4*2048 + a 2048 (64-row layout kept)
#define XRAW 30720              // 3 * TSTG
#define XSTG 4352               // [32][136]
#define XSTR 136
#define AOFF 43776              // XRAW + 3*XSTG ; A double buffer 2*2304
#define SMEM_WORDS 48384        // 193536 bytes
#define HS_STRIDE 132

extern __shared__ float sm[];

__device__ __forceinline__ uint32_t tf32r(float f) {
    uint32_t r;
    asm("cvt.rna.tf32.f32 %0, %1;" : "=r"(r) : "f"(f));
    return r;
}
__device__ __forceinline__ void mma8(float* c, uint32_t a0, uint32_t a1,
                                     uint32_t a2, uint32_t a3,
                                     uint32_t b0, uint32_t b1) {
    asm volatile(
        "mma.sync.aligned.m16n8k8.row.col.f32.tf32.tf32.f32 "
        "{%0,%1,%2,%3}, {%4,%5,%6,%7}, {%8,%9}, {%0,%1,%2,%3};"
        : "+f"(c[0]), "+f"(c[1]), "+f"(c[2]), "+f"(c[3])
        : "r"(a0), "r"(a1), "r"(a2), "r"(a3), "r"(b0), "r"(b1));
}
__device__ __forceinline__ void cpa16(uint32_t dst, const float* src) {
    asm volatile("cp.async.cg.shared.global [%0], [%1], 16;" :: "r"(dst), "l"(src));
}
#define CP_COMMIT() asm volatile("cp.async.commit_group;" ::: "memory")
#define CP_WAIT1()  asm volatile("cp.async.wait_group 1;" ::: "memory")
#define STS128(ad, x, y, z, w) \
    asm volatile("st.shared.v4.b32 [%0], {%1,%2,%3,%4};" :: \
        "r"(ad), "r"(x), "r"(y), "r"(z), "r"(w) : "memory")

__global__ __launch_bounds__(TPB, 1)
void ggd_kernel(const float* __restrict__ theta, const float* __restrict__ T,
                const float* __restrict__ x, const float* __restrict__ a,
                const float* __restrict__ alpha, const float* __restrict__ W,
                const float* __restrict__ bias, float* __restrict__ out) {
    const int tid = threadIdx.x;
    const int lane = tid & 31, wid = tid >> 5;
    const int g = lane >> 2, tig = lane & 3;
    const int wr = wid & 1, wc = wid >> 1;
    const int i0 = blockIdx.x * BM;
    const size_t slice = (size_t)NN * NN;

    uint32_t sbase;
    asm("{ .reg .u64 t; cvta.to.shared.u64 t, %1; cvt.u32.u64 %0, t; }"
        : "=r"(sbase) : "l"(sm));

    // ---- cp.async source/dst precompute ----
    // T: 8 chunks/thread over 4 slices x 64 rows x 8 quads; rows >=56 clamp to 55.
    const float* srcT[8]; uint32_t dstT[8];
#pragma unroll
    for (int q = 0; q < 8; q++) {
        int c = tid + q * 256;
        int k = c >> 9, rem = c & 511, r = rem >> 3, cc = (rem & 7) * 4;
        int rr = r < BM ? r : BM - 1;
        int row = i0 + rr; if (row > NN - 1) row = NN - 1;
        srcT[q] = T + (size_t)k * slice + (size_t)row * NN + cc;
        dstT[q] = (uint32_t)c * 16;
    }
    int ra0 = tid >> 3;                       // 0..31 (< BM, valid)
    int rowa0 = i0 + ra0; if (rowa0 > NN - 1) rowa0 = NN - 1;
    int ra1 = 32 + (tid >> 3); if (ra1 > BM - 1) ra1 = BM - 1;
    int rowa1 = i0 + ra1; if (rowa1 > NN - 1) rowa1 = NN - 1;
    const float* srcA0 = a + (size_t)rowa0 * NN + (tid & 7) * 4;
    const float* srcA1 = a + (size_t)rowa1 * NN + (tid & 7) * 4;
    const uint32_t dstA0 = 8192 * 4 + (uint32_t)tid * 16;
    const uint32_t dstA1 = dstA0 + 256 * 16;
    const float* srcX[4]; uint32_t dstX[4];
#pragma unroll
    for (int q = 0; q < 4; q++) {
        int c = tid + q * 256;
        int row = c >> 5, cc = (c & 31) * 4;
        srcX[q] = x + (size_t)row * DDIM + cc;
        dstX[q] = (uint32_t)(row * XSTR + cc) * 4;
    }

#define ISSUE(J0, STG) do {                                                    \
    uint32_t _tb = sbase + (uint32_t)((STG) * TSTG) * 4;                       \
    uint32_t _xb = sbase + (uint32_t)(XRAW + (STG) * XSTG) * 4;                \
    _Pragma("unroll") for (int _q = 0; _q < 8; _q++)                           \
        cpa16(_tb + dstT[_q], srcT[_q] + (J0));                                \
    cpa16(_tb + dstA0, srcA0 + (J0));                                          \
    cpa16(_tb + dstA1, srcA1 + (J0));                                          \
    _Pragma("unroll") for (int _q = 0; _q < 4; _q++)                           \
        cpa16(_xb + dstX[_q], srcX[_q] + (size_t)(J0) * DDIM);                 \
} while (0)

    const float th0 = __ldg(theta), th1 = __ldg(theta + 1),
                th2 = __ldg(theta + 2), th3 = __ldg(theta + 3);

    float acc[2][4][4];
#pragma unroll
    for (int mi = 0; mi < 2; mi++)
#pragma unroll
        for (int nf = 0; nf < 4; nf++)
#pragma unroll
            for (int e = 0; e < 4; e++) acc[mi][nf][e] = 0.f;

    // prologue: tiles 0 and 1 in flight
    ISSUE(0, 0);  CP_COMMIT();
    ISSUE(BK, 1); CP_COMMIT();

    int s3 = 0;   // t % 3
    for (int t = 0; t < NT; t++) {
        CP_WAIT1();            // group t complete
        __syncthreads();       // arrivals visible; t-1's reads all done

        if (t + 2 < NT) {
            int stg = s3 + 2; if (stg >= 3) stg -= 3;
            ISSUE((t + 2) * BK, stg);
        }
        CP_COMMIT();

        // ---- build: q -> A[t&1]; cvt x in place ----
        const float* traw = sm + s3 * TSTG;
        const float* araw = traw + 8192;
        float* Xb = sm + XRAW + s3 * XSTG;
        uint32_t Abad = sbase + (uint32_t)(AOFF + (t & 1) * 2304) * 4;
#pragma unroll
        for (int qq = 0; qq < 2; qq++) {
            int idx = tid + qq * 256;
            int row = idx >> 3, c4 = (idx & 7) * 4;
            float4 t0 = *(const float4*)(traw + row * 32 + c4);
            float4 t1 = *(const float4*)(traw + 2048 + row * 32 + c4);
            float4 t2 = *(const float4*)(traw + 4096 + row * 32 + c4);
            float4 t3 = *(const float4*)(traw + 6144 + row * 32 + c4);
            float4 av = *(const float4*)(araw + row * 32 + c4);
            uint32_t qx = tf32r((th0*t0.x + th1*t1.x + th2*t2.x + th3*t3.x) * av.x);
            uint32_t qy = tf32r((th0*t0.y + th1*t1.y + th2*t2.y + th3*t3.y) * av.y);
            uint32_t qz = tf32r((th0*t0.z + th1*t1.z + th2*t2.z + th3*t3.z) * av.z);
            uint32_t qw = tf32r((th0*t0.w + th1*t1.w + th2*t2.w + th3*t3.w) * av.w);
            STS128(Abad + (uint32_t)(row * 36 + c4) * 4, qx, qy, qz, qw);
        }
#pragma unroll
        for (int qq = 0; qq < 4; qq++) {
            int idx = tid + qq * 256;
            float* p = Xb + (idx >> 5) * XSTR + (idx & 31) * 4;
            float4 v = *(const float4*)p;
            uint32_t pa;
            asm("{ .reg .u64 t; cvta.to.shared.u64 t, %1; cvt.u32.u64 %0, t; }"
                : "=r"(pa) : "l"(p));
            STS128(pa, tf32r(v.x), tf32r(v.y), tf32r(v.z), tf32r(v.w));
        }
        __syncthreads();       // A + converted X visible

        // ---- mma ----
        const uint32_t* As = (const uint32_t*)(sm + AOFF + (t & 1) * 2304);
        const uint32_t* Xs = (const uint32_t*)Xb;
#pragma unroll
        for (int ks = 0; ks < 4; ks++) {
            uint32_t af[2][4];
#pragma unroll
            for (int mi = 0; mi < 2; mi++) {
                const uint32_t* ap = As + (wr*32 + mi*16 + g) * 36 + ks*8 + tig;
                af[mi][0] = ap[0];
                af[mi][1] = ap[8 * 36];
                af[mi][2] = ap[4];
                af[mi][3] = ap[8 * 36 + 4];
            }
#pragma unroll
            for (int nfl = 0; nfl < 4; nfl++) {
                const int n = (wc*4 + nfl)*8 + g;
                uint32_t b0 = Xs[(ks*8 + tig)     * XSTR + n];
                uint32_t b1 = Xs[(ks*8 + tig + 4) * XSTR + n];
#pragma unroll
                for (int mi = 0; mi < 2; mi++)
                    mma8(acc[mi][nfl], af[mi][0], af[mi][1], af[mi][2], af[mi][3],
                         b0, b1);
            }
        }
        if (++s3 == 3) s3 = 0;
    }

    // ---- epilogue: acc -> hs, prelu + projection ----
    __syncthreads();
    float* hs = sm;   // [64][HS_STRIDE]
#pragma unroll
    for (int mi = 0; mi < 2; mi++)
#pragma unroll
        for (int nfl = 0; nfl < 4; nfl++) {
            const int col = (wc*4 + nfl)*8 + tig*2;
            const int r0 = wr*32 + mi*16 + g;
            *(float2*)(hs + r0 * HS_STRIDE + col) =
                make_float2(acc[mi][nfl][0], acc[mi][nfl][1]);
            *(float2*)(hs + (r0 + 8) * HS_STRIDE + col) =
                make_float2(acc[mi][nfl][2], acc[mi][nfl][3]);
        }
    __syncthreads();

    const int tx = tid & 15, ty = tid >> 4;
    const int tx8 = tx * 8, ty4 = ty * 4;
    float oa[4][8];
#pragma unroll
    for (int m = 0; m < 4; m++)
#pragma unroll
        for (int u = 0; u < 8; u++) oa[m][u] = 0.f;

    for (int c4 = 0; c4 < 32; c4++) {
        float4 al = __ldg((const float4*)(alpha + c4 * 4));
        float4 wv[8];
#pragma unroll
        for (int u = 0; u < 8; u++)
            wv[u] = __ldg((const float4*)(W + (size_t)(tx8 + u) * DDIM + c4 * 4));
#pragma unroll
        for (int m = 0; m < 4; m++) {
            float4 hv = *(const float4*)(hs + (ty4 + m) * HS_STRIDE + c4 * 4);
            hv.x = hv.x > 0.f ? hv.x : al.x * hv.x;
            hv.y = hv.y > 0.f ? hv.y : al.y * hv.y;
            hv.z = hv.z > 0.f ? hv.z : al.z * hv.z;
            hv.w = hv.w > 0.f ? hv.w : al.w * hv.w;
#pragma unroll
            for (int u = 0; u < 8; u++)
                oa[m][u] += hv.x * wv[u].x + hv.y * wv[u].y +
                            hv.z * wv[u].z + hv.w * wv[u].w;
        }
    }
    float4 b0 = __ldg((const float4*)(bias + tx8));
    float4 b1 = __ldg((const float4*)(bias + tx8 + 4));
#pragma unroll
    for (int m = 0; m < 4; m++) {
        int r = ty4 + m;
        int grow = i0 + r;
        if (r < BM && grow < NN) {
            size_t go = (size_t)grow * DDIM;
            *(float4*)(out + go + tx8) =
                make_float4(oa[m][0] + b0.x, oa[m][1] + b0.y,
                            oa[m][2] + b0.z, oa[m][3] + b0.w);
            *(float4*)(out + go + tx8 + 4) =
                make_float4(oa[m][4] + b1.x, oa[m][5] + b1.y,
                            oa[m][6] + b1.z, oa[m][7] + b1.w);
        }
    }
}

extern "C" void kernel_launch(void* const* d_in, const int* in_sizes, int n_in,
                              void* d_out, int out_size) {
    const float* theta = (const float*)d_in[0];
    const float* T     = (const float*)d_in[1];
    const float* x     = (const float*)d_in[2];
    const float* a     = (const float*)d_in[3];
    const float* alpha = (const float*)d_in[4];
    const float* W     = (const float*)d_in[5];
    const float* bias  = (const float*)d_in[6];
    (void)in_sizes; (void)n_in; (void)out_size;

    cudaFuncSetAttribute(ggd_kernel, cudaFuncAttributeMaxDynamicSharedMemorySize,
                         SMEM_WORDS * 4);
    ggd_kernel<<<(NN + BM - 1) / BM, TPB, SMEM_WORDS * 4>>>(theta, T, x, a, alpha,
                                                            W, bias, (float*)d_out);
}

// round 14
// speedup vs baseline: 1.1234x; 1.0543x over previous
#include <cuda_runtime.h>
#include <cstdint>

// GeneralizedGraphDiffusion: out = prelu((sum_k theta_k*T_k * a) @ x) @ W^T + b
// N=8192, D=128, K=4.
// R14: 64-K iterations (2 ring slots per iter, 4-slot ring) -> per-tile fixed
// cost halved. 'a' register-staged (never in smem). mma.sync tf32, 8 warps,
// grid 128, BM 64. One wait + two syncs per 64 K.

#define NN 8192
#define DDIM 128
#define BM 64
#define NT 128                  // iterations of 64 K-columns
#define TPB 256

// smem float offsets
#define SLOT 12544              // T 8192 + X 4352
#define XOFF 8192               // X within slot
#define XSTR 136
#define AOFF 50176              // 4*SLOT ; A = [2][64][36] = 4608
#define SMEM_WORDS 54784        // 219136 bytes
#define HS_STRIDE 132

extern __shared__ float sm[];

__device__ __forceinline__ uint32_t tf32r(float f) {
    uint32_t r;
    asm("cvt.rna.tf32.f32 %0, %1;" : "=r"(r) : "f"(f));
    return r;
}
__device__ __forceinline__ void mma8(float* c, uint32_t a0, uint32_t a1,
                                     uint32_t a2, uint32_t a3,
                                     uint32_t b0, uint32_t b1) {
    asm volatile(
        "mma.sync.aligned.m16n8k8.row.col.f32.tf32.tf32.f32 "
        "{%0,%1,%2,%3}, {%4,%5,%6,%7}, {%8,%9}, {%0,%1,%2,%3};"
        : "+f"(c[0]), "+f"(c[1]), "+f"(c[2]), "+f"(c[3])
        : "r"(a0), "r"(a1), "r"(a2), "r"(a3), "r"(b0), "r"(b1));
}
__device__ __forceinline__ void cpa16(uint32_t dst, const float* src) {
    asm volatile("cp.async.cg.shared.global [%0], [%1], 16;" :: "r"(dst), "l"(src));
}
#define CP_COMMIT() asm volatile("cp.async.commit_group;" ::: "memory")
#define CP_WAIT0()  asm volatile("cp.async.wait_group 0;" ::: "memory")
#define STS128(ad, x, y, z, w) \
    asm volatile("st.shared.v4.b32 [%0], {%1,%2,%3,%4};" :: \
        "r"(ad), "r"(x), "r"(y), "r"(z), "r"(w) : "memory")

__global__ __launch_bounds__(TPB, 1)
void ggd_kernel(const float* __restrict__ theta, const float* __restrict__ T,
                const float* __restrict__ x, const float* __restrict__ a,
                const float* __restrict__ alpha, const float* __restrict__ W,
                const float* __restrict__ bias, float* __restrict__ out) {
    const int tid = threadIdx.x;
    const int lane = tid & 31, wid = tid >> 5;
    const int g = lane >> 2, tig = lane & 3;
    const int wr = wid & 1, wc = wid >> 1;
    const int i0 = blockIdx.x * BM;
    const size_t slice = (size_t)NN * NN;

    uint32_t sbase;
    asm("{ .reg .u64 t; cvta.to.shared.u64 t, %1; cvt.u32.u64 %0, t; }"
        : "=r"(sbase) : "l"(sm));

    // ---- cp.async precompute (per 32-K slot: T 2048 chunks, X 1024 chunks) ----
    const float* srcT[8]; uint32_t dstT[8];
#pragma unroll
    for (int q = 0; q < 8; q++) {
        int c = tid + q * 256;
        int k = c >> 9, rem = c & 511, r = rem >> 3, cc = (rem & 7) * 4;
        srcT[q] = T + (size_t)k * slice + (size_t)(i0 + r) * NN + cc;
        dstT[q] = (uint32_t)c * 16;
    }
    const float* srcX[4]; uint32_t dstX[4];
#pragma unroll
    for (int q = 0; q < 4; q++) {
        int c = tid + q * 256;
        int row = c >> 5, cc = (c & 31) * 4;
        srcX[q] = x + (size_t)row * DDIM + cc;
        dstX[q] = (uint32_t)(XOFF + row * XSTR + cc) * 4;
    }

#define ISSUE(J0, STG) do {                                                    \
    uint32_t _sb = sbase + (uint32_t)((STG) * SLOT) * 4;                       \
    _Pragma("unroll") for (int _q = 0; _q < 8; _q++)                           \
        cpa16(_sb + dstT[_q], srcT[_q] + (J0));                                \
    _Pragma("unroll") for (int _q = 0; _q < 4; _q++)                           \
        cpa16(_sb + dstX[_q], srcX[_q] + (size_t)(J0) * DDIM);                 \
} while (0)

    // ---- 'a' register staging: quads matching build assignment ----
    const size_t rbA0 = (size_t)(i0 + (tid >> 3)) * NN + (tid & 7) * 4;        // rows 0..31
    const size_t rbA1 = rbA0 + (size_t)32 * NN;                                // rows 32..63
    float4 pa[4];   // [half][qq]

#define LOADR_A(J0) do {                                                       \
    pa[0] = *(const float4*)(a + rbA0 + (J0));                                 \
    pa[1] = *(const float4*)(a + rbA1 + (J0));                                 \
    pa[2] = *(const float4*)(a + rbA0 + (J0) + 32);                            \
    pa[3] = *(const float4*)(a + rbA1 + (J0) + 32);                            \
} while (0)

    const float th0 = __ldg(theta), th1 = __ldg(theta + 1),
                th2 = __ldg(theta + 2), th3 = __ldg(theta + 3);

    float acc[2][4][4];
#pragma unroll
    for (int mi = 0; mi < 2; mi++)
#pragma unroll
        for (int nf = 0; nf < 4; nf++)
#pragma unroll
            for (int e = 0; e < 4; e++) acc[mi][nf][e] = 0.f;

    // prologue: iteration 0's two slots in flight; a(0) in regs
    ISSUE(0, 0);
    ISSUE(32, 1);
    CP_COMMIT();
    LOADR_A(0);

    for (int t = 0; t < NT; t++) {
        CP_WAIT0();            // both slots of iter t arrived
        __syncthreads();       // visible; everyone past build/mma(t-1)

        const int s0 = (2 * t) & 3;
        if (t + 1 < NT) {      // slots (2t+2)&3, (2t+3)&3 — disjoint from s0,s0+1
            ISSUE((t + 1) * 64,      (2 * t + 2) & 3);
            ISSUE((t + 1) * 64 + 32, (2 * t + 3) & 3);
            CP_COMMIT();
        }

        // ---- build both halves: q -> A[h], cvt X in place ----
#pragma unroll
        for (int h = 0; h < 2; h++) {
            const float* traw = sm + ((s0 + h) & 3) * SLOT;
            uint32_t Abad = sbase + (uint32_t)(AOFF + h * 2304) * 4;
#pragma unroll
            for (int qq = 0; qq < 2; qq++) {
                int idx = tid + qq * 256;
                int row = idx >> 3, c4 = (idx & 7) * 4;
                float4 t0 = *(const float4*)(traw + row * 32 + c4);
                float4 t1 = *(const float4*)(traw + 2048 + row * 32 + c4);
                float4 t2 = *(const float4*)(traw + 4096 + row * 32 + c4);
                float4 t3 = *(const float4*)(traw + 6144 + row * 32 + c4);
                float4 av = pa[h * 2 + qq];
                uint32_t qx = tf32r((th0*t0.x + th1*t1.x + th2*t2.x + th3*t3.x) * av.x);
                uint32_t qy = tf32r((th0*t0.y + th1*t1.y + th2*t2.y + th3*t3.y) * av.y);
                uint32_t qz = tf32r((th0*t0.z + th1*t1.z + th2*t2.z + th3*t3.z) * av.z);
                uint32_t qw = tf32r((th0*t0.w + th1*t1.w + th2*t2.w + th3*t3.w) * av.w);
                STS128(Abad + (uint32_t)(row * 36 + c4) * 4, qx, qy, qz, qw);
            }
            float* Xb = sm + ((s0 + h) & 3) * SLOT + XOFF;
#pragma unroll
            for (int qq = 0; qq < 4; qq++) {
                int idx = tid + qq * 256;
                float* p = Xb + (idx >> 5) * XSTR + (idx & 31) * 4;
                float4 v = *(const float4*)p;
                uint32_t pad;
                asm("{ .reg .u64 t; cvta.to.shared.u64 t, %1; cvt.u32.u64 %0, t; }"
                    : "=r"(pad) : "l"(p));
                STS128(pad, tf32r(v.x), tf32r(v.y), tf32r(v.z), tf32r(v.w));
            }
        }
        __syncthreads();       // A + converted X visible

        if (t + 1 < NT) LOADR_A((t + 1) * 64);   // a(t+1) lands during mma(t)

        // ---- mma both halves ----
#pragma unroll
        for (int h = 0; h < 2; h++) {
            const uint32_t* As = (const uint32_t*)(sm + AOFF + h * 2304);
            const uint32_t* Xs = (const uint32_t*)(sm + ((s0 + h) & 3) * SLOT + XOFF);
#pragma unroll
            for (int ks = 0; ks < 4; ks++) {
                uint32_t af[2][4];
#pragma unroll
                for (int mi = 0; mi < 2; mi++) {
                    const uint32_t* ap = As + (wr*32 + mi*16 + g) * 36 + ks*8 + tig;
                    af[mi][0] = ap[0];
                    af[mi][1] = ap[8 * 36];
                    af[mi][2] = ap[4];
                    af[mi][3] = ap[8 * 36 + 4];
                }
#pragma unroll
                for (int nfl = 0; nfl < 4; nfl++) {
                    const int n = (wc*4 + nfl)*8 + g;
                    uint32_t b0 = Xs[(ks*8 + tig)     * XSTR + n];
                    uint32_t b1 = Xs[(ks*8 + tig + 4) * XSTR + n];
#pragma unroll
                    for (int mi = 0; mi < 2; mi++)
                        mma8(acc[mi][nfl], af[mi][0], af[mi][1], af[mi][2], af[mi][3],
                             b0, b1);
                }
            }
        }
    }

    // ---- epilogue: acc -> hs, prelu + projection ----
    __syncthreads();
    float* hs = sm;   // [64][HS_STRIDE]
#pragma unroll
    for (int mi = 0; mi < 2; mi++)
#pragma unroll
        for (int nfl = 0; nfl < 4; nfl++) {
            const int col = (wc*4 + nfl)*8 + tig*2;
            const int r0 = wr*32 + mi*16 + g;
            *(float2*)(hs + r0 * HS_STRIDE + col) =
                make_float2(acc[mi][nfl][0], acc[mi][nfl][1]);
            *(float2*)(hs + (r0 + 8) * HS_STRIDE + col) =
                make_float2(acc[mi][nfl][2], acc[mi][nfl][3]);
        }
    __syncthreads();

    const int tx = tid & 15, ty = tid >> 4;
    const int tx8 = tx * 8, ty4 = ty * 4;
    float oa[4][8];
#pragma unroll
    for (int m = 0; m < 4; m++)
#pragma unroll
        for (int u = 0; u < 8; u++) oa[m][u] = 0.f;

    for (int c4 = 0; c4 < 32; c4++) {
        float4 al = __ldg((const float4*)(alpha + c4 * 4));
        float4 wv[8];
#pragma unroll
        for (int u = 0; u < 8; u++)
            wv[u] = __ldg((const float4*)(W + (size_t)(tx8 + u) * DDIM + c4 * 4));
#pragma unroll
        for (int m = 0; m < 4; m++) {
            float4 hv = *(const float4*)(hs + (ty4 + m) * HS_STRIDE + c4 * 4);
            hv.x = hv.x > 0.f ? hv.x : al.x * hv.x;
            hv.y = hv.y > 0.f ? hv.y : al.y * hv.y;
            hv.z = hv.z > 0.f ? hv.z : al.z * hv.z;
            hv.w = hv.w > 0.f ? hv.w : al.w * hv.w;
#pragma unroll
            for (int u = 0; u < 8; u++)
                oa[m][u] += hv.x * wv[u].x + hv.y * wv[u].y +
                            hv.z * wv[u].z + hv.w * wv[u].w;
        }
    }
    float4 b0 = __ldg((const float4*)(bias + tx8));
    float4 b1 = __ldg((const float4*)(bias + tx8 + 4));
#pragma unroll
    for (int m = 0; m < 4; m++) {
        size_t go = (size_t)(i0 + ty4 + m) * DDIM;
        *(float4*)(out + go + tx8) =
            make_float4(oa[m][0] + b0.x, oa[m][1] + b0.y,
                        oa[m][2] + b0.z, oa[m][3] + b0.w);
        *(float4*)(out + go + tx8 + 4) =
            make_float4(oa[m][4] + b1.x, oa[m][5] + b1.y,
                        oa[m][6] + b1.z, oa[m][7] + b1.w);
    }
}

extern "C" void kernel_launch(void* const* d_in, const int* in_sizes, int n_in,
                              void* d_out, int out_size) {
    const float* theta = (const float*)d_in[0];
    const float* T     = (const float*)d_in[1];
    const float* x     = (const float*)d_in[2];
    const float* a     = (const float*)d_in[3];
    const float* alpha = (const float*)d_in[4];
    const float* W     = (const float*)d_in[5];
    const float* bias  = (const float*)d_in[6];
    (void)in_sizes; (void)n_in; (void)out_size;

    cudaFuncSetAttribute(ggd_kernel, cudaFuncAttributeMaxDynamicSharedMemorySize,
                         SMEM_WORDS * 4);
    ggd_kernel<<<NN / BM, TPB, SMEM_WORDS * 4>>>(theta, T, x, a, alpha, W, bias,
                                                 (float*)d_out);
}

// round 15
// speedup vs baseline: 1.2896x; 1.1480x over previous
#include <cuda_runtime.h>
#include <cstdint>

// GeneralizedGraphDiffusion: out = prelu((sum_k theta_k*T_k * a) @ x) @ W^T + b
// N=8192, D=128, K=4.
// R15: R14 (64-K iters, 4-slot ring, a register-staged) + x pre-converted to
// tf32 ONCE into __device__ scratch -> X build step deleted from the mainloop.
// mma.sync tf32, 8 warps, grid 128, BM 64.

#define NN 8192
#define DDIM 128
#define BM 64
#define NT 128                  // iterations of 64 K-columns
#define TPB 256

// smem float offsets
#define SLOT 12544              // T 8192 + X 4352
#define XOFF 8192               // X within slot
#define XSTR 136
#define AOFF 50176              // 4*SLOT ; A = [2][64][36] = 4608
#define SMEM_WORDS 54784        // 219136 bytes
#define HS_STRIDE 132

__device__ float g_xconv[NN * DDIM];   // tf32-rounded x

extern __shared__ float sm[];

__device__ __forceinline__ uint32_t tf32r(float f) {
    uint32_t r;
    asm("cvt.rna.tf32.f32 %0, %1;" : "=r"(r) : "f"(f));
    return r;
}
__device__ __forceinline__ void mma8(float* c, uint32_t a0, uint32_t a1,
                                     uint32_t a2, uint32_t a3,
                                     uint32_t b0, uint32_t b1) {
    asm volatile(
        "mma.sync.aligned.m16n8k8.row.col.f32.tf32.tf32.f32 "
        "{%0,%1,%2,%3}, {%4,%5,%6,%7}, {%8,%9}, {%0,%1,%2,%3};"
        : "+f"(c[0]), "+f"(c[1]), "+f"(c[2]), "+f"(c[3])
        : "r"(a0), "r"(a1), "r"(a2), "r"(a3), "r"(b0), "r"(b1));
}
__device__ __forceinline__ void cpa16(uint32_t dst, const float* src) {
    asm volatile("cp.async.cg.shared.global [%0], [%1], 16;" :: "r"(dst), "l"(src));
}
#define CP_COMMIT() asm volatile("cp.async.commit_group;" ::: "memory")
#define CP_WAIT0()  asm volatile("cp.async.wait_group 0;" ::: "memory")
#define STS128(ad, x, y, z, w) \
    asm volatile("st.shared.v4.b32 [%0], {%1,%2,%3,%4};" :: \
        "r"(ad), "r"(x), "r"(y), "r"(z), "r"(w) : "memory")

// ---- pre-pass: convert x to tf32 once ----
__global__ __launch_bounds__(256, 1)
void xconv_kernel(const float* __restrict__ x) {
    int idx = blockIdx.x * 256 + threadIdx.x;   // float4 index
#pragma unroll
    for (int q = 0; q < 8; q++) {
        int e = idx + q * 32768;
        float4 v = *(const float4*)(x + (size_t)e * 4);
        uint4 o;
        o.x = tf32r(v.x); o.y = tf32r(v.y); o.z = tf32r(v.z); o.w = tf32r(v.w);
        *(uint4*)(g_xconv + (size_t)e * 4) = o;
    }
}

__global__ __launch_bounds__(TPB, 1)
void ggd_kernel(const float* __restrict__ theta, const float* __restrict__ T,
                const float* __restrict__ a,
                const float* __restrict__ alpha, const float* __restrict__ W,
                const float* __restrict__ bias, float* __restrict__ out) {
    const int tid = threadIdx.x;
    const int lane = tid & 31, wid = tid >> 5;
    const int g = lane >> 2, tig = lane & 3;
    const int wr = wid & 1, wc = wid >> 1;
    const int i0 = blockIdx.x * BM;
    const size_t slice = (size_t)NN * NN;

    uint32_t sbase;
    asm("{ .reg .u64 t; cvta.to.shared.u64 t, %1; cvt.u32.u64 %0, t; }"
        : "=r"(sbase) : "l"(sm));

    // ---- cp.async precompute (per 32-K slot: T 2048 chunks, X 1024 chunks) ----
    const float* srcT[8]; uint32_t dstT[8];
#pragma unroll
    for (int q = 0; q < 8; q++) {
        int c = tid + q * 256;
        int k = c >> 9, rem = c & 511, r = rem >> 3, cc = (rem & 7) * 4;
        srcT[q] = T + (size_t)k * slice + (size_t)(i0 + r) * NN + cc;
        dstT[q] = (uint32_t)c * 16;
    }
    const float* srcX[4]; uint32_t dstX[4];
#pragma unroll
    for (int q = 0; q < 4; q++) {
        int c = tid + q * 256;
        int row = c >> 5, cc = (c & 31) * 4;
        srcX[q] = g_xconv + (size_t)row * DDIM + cc;
        dstX[q] = (uint32_t)(XOFF + row * XSTR + cc) * 4;
    }

#define ISSUE(J0, STG) do {                                                    \
    uint32_t _sb = sbase + (uint32_t)((STG) * SLOT) * 4;                       \
    _Pragma("unroll") for (int _q = 0; _q < 8; _q++)                           \
        cpa16(_sb + dstT[_q], srcT[_q] + (J0));                                \
    _Pragma("unroll") for (int _q = 0; _q < 4; _q++)                           \
        cpa16(_sb + dstX[_q], srcX[_q] + (size_t)(J0) * DDIM);                 \
} while (0)

    // ---- 'a' register staging: quads matching build assignment ----
    const size_t rbA0 = (size_t)(i0 + (tid >> 3)) * NN + (tid & 7) * 4;        // rows 0..31
    const size_t rbA1 = rbA0 + (size_t)32 * NN;                                // rows 32..63
    float4 pa[4];   // [half][qq]

#define LOADR_A(J0) do {                                                       \
    pa[0] = *(const float4*)(a + rbA0 + (J0));                                 \
    pa[1] = *(const float4*)(a + rbA1 + (J0));                                 \
    pa[2] = *(const float4*)(a + rbA0 + (J0) + 32);                            \
    pa[3] = *(const float4*)(a + rbA1 + (J0) + 32);                            \
} while (0)

    const float th0 = __ldg(theta), th1 = __ldg(theta + 1),
                th2 = __ldg(theta + 2), th3 = __ldg(theta + 3);

    float acc[2][4][4];
#pragma unroll
    for (int mi = 0; mi < 2; mi++)
#pragma unroll
        for (int nf = 0; nf < 4; nf++)
#pragma unroll
            for (int e = 0; e < 4; e++) acc[mi][nf][e] = 0.f;

    // prologue: iteration 0's two slots in flight; a(0) in regs
    ISSUE(0, 0);
    ISSUE(32, 1);
    CP_COMMIT();
    LOADR_A(0);

    for (int t = 0; t < NT; t++) {
        CP_WAIT0();            // both slots of iter t arrived
        __syncthreads();       // visible; everyone past build/mma(t-1)

        const int s0 = (2 * t) & 3;
        if (t + 1 < NT) {      // slots (2t+2)&3, (2t+3)&3 — disjoint from s0,s0+1
            ISSUE((t + 1) * 64,      (2 * t + 2) & 3);
            ISSUE((t + 1) * 64 + 32, (2 * t + 3) & 3);
            CP_COMMIT();
        }

        // ---- build A only (X already tf32 from pre-pass) ----
#pragma unroll
        for (int h = 0; h < 2; h++) {
            const float* traw = sm + ((s0 + h) & 3) * SLOT;
            uint32_t Abad = sbase + (uint32_t)(AOFF + h * 2304) * 4;
#pragma unroll
            for (int qq = 0; qq < 2; qq++) {
                int idx = tid + qq * 256;
                int row = idx >> 3, c4 = (idx & 7) * 4;
                float4 t0 = *(const float4*)(traw + row * 32 + c4);
                float4 t1 = *(const float4*)(traw + 2048 + row * 32 + c4);
                float4 t2 = *(const float4*)(traw + 4096 + row * 32 + c4);
                float4 t3 = *(const float4*)(traw + 6144 + row * 32 + c4);
                float4 av = pa[h * 2 + qq];
                uint32_t qx = tf32r((th0*t0.x + th1*t1.x + th2*t2.x + th3*t3.x) * av.x);
                uint32_t qy = tf32r((th0*t0.y + th1*t1.y + th2*t2.y + th3*t3.y) * av.y);
                uint32_t qz = tf32r((th0*t0.z + th1*t1.z + th2*t2.z + th3*t3.z) * av.z);
                uint32_t qw = tf32r((th0*t0.w + th1*t1.w + th2*t2.w + th3*t3.w) * av.w);
                STS128(Abad + (uint32_t)(row * 36 + c4) * 4, qx, qy, qz, qw);
            }
        }
        __syncthreads();       // A visible

        if (t + 1 < NT) LOADR_A((t + 1) * 64);   // a(t+1) lands during mma(t)

        // ---- mma both halves ----
#pragma unroll
        for (int h = 0; h < 2; h++) {
            const uint32_t* As = (const uint32_t*)(sm + AOFF + h * 2304);
            const uint32_t* Xs = (const uint32_t*)(sm + ((s0 + h) & 3) * SLOT + XOFF);
#pragma unroll
            for (int ks = 0; ks < 4; ks++) {
                uint32_t af[2][4];
#pragma unroll
                for (int mi = 0; mi < 2; mi++) {
                    const uint32_t* ap = As + (wr*32 + mi*16 + g) * 36 + ks*8 + tig;
                    af[mi][0] = ap[0];
                    af[mi][1] = ap[8 * 36];
                    af[mi][2] = ap[4];
                    af[mi][3] = ap[8 * 36 + 4];
                }
#pragma unroll
                for (int nfl = 0; nfl < 4; nfl++) {
                    const int n = (wc*4 + nfl)*8 + g;
                    uint32_t b0 = Xs[(ks*8 + tig)     * XSTR + n];
                    uint32_t b1 = Xs[(ks*8 + tig + 4) * XSTR + n];
#pragma unroll
                    for (int mi = 0; mi < 2; mi++)
                        mma8(acc[mi][nfl], af[mi][0], af[mi][1], af[mi][2], af[mi][3],
                             b0, b1);
                }
            }
        }
    }

    // ---- epilogue: acc -> hs, prelu + projection ----
    __syncthreads();
    float* hs = sm;   // [64][HS_STRIDE]
#pragma unroll
    for (int mi = 0; mi < 2; mi++)
#pragma unroll
        for (int nfl = 0; nfl < 4; nfl++) {
            const int col = (wc*4 + nfl)*8 + tig*2;
            const int r0 = wr*32 + mi*16 + g;
            *(float2*)(hs + r0 * HS_STRIDE + col) =
                make_float2(acc[mi][nfl][0], acc[mi][nfl][1]);
            *(float2*)(hs + (r0 + 8) * HS_STRIDE + col) =
                make_float2(acc[mi][nfl][2], acc[mi][nfl][3]);
        }
    __syncthreads();

    const int tx = tid & 15, ty = tid >> 4;
    const int tx8 = tx * 8, ty4 = ty * 4;
    float oa[4][8];
#pragma unroll
    for (int m = 0; m < 4; m++)
#pragma unroll
        for (int u = 0; u < 8; u++) oa[m][u] = 0.f;

    for (int c4 = 0; c4 < 32; c4++) {
        float4 al = __ldg((const float4*)(alpha + c4 * 4));
        float4 wv[8];
#pragma unroll
        for (int u = 0; u < 8; u++)
            wv[u] = __ldg((const float4*)(W + (size_t)(tx8 + u) * DDIM + c4 * 4));
#pragma unroll
        for (int m = 0; m < 4; m++) {
            float4 hv = *(const float4*)(hs + (ty4 + m) * HS_STRIDE + c4 * 4);
            hv.x = hv.x > 0.f ? hv.x : al.x * hv.x;
            hv.y = hv.y > 0.f ? hv.y : al.y * hv.y;
            hv.z = hv.z > 0.f ? hv.z : al.z * hv.z;
            hv.w = hv.w > 0.f ? hv.w : al.w * hv.w;
#pragma unroll
            for (int u = 0; u < 8; u++)
                oa[m][u] += hv.x * wv[u].x + hv.y * wv[u].y +
                            hv.z * wv[u].z + hv.w * wv[u].w;
        }
    }
    float4 b0 = __ldg((const float4*)(bias + tx8));
    float4 b1 = __ldg((const float4*)(bias + tx8 + 4));
#pragma unroll
    for (int m = 0; m < 4; m++) {
        size_t go = (size_t)(i0 + ty4 + m) * DDIM;
        *(float4*)(out + go + tx8) =
            make_float4(oa[m][0] + b0.x, oa[m][1] + b0.y,
                        oa[m][2] + b0.z, oa[m][3] + b0.w);
        *(float4*)(out + go + tx8 + 4) =
            make_float4(oa[m][4] + b1.x, oa[m][5] + b1.y,
                        oa[m][6] + b1.z, oa[m][7] + b1.w);
    }
}

extern "C" void kernel_launch(void* const* d_in, const int* in_sizes, int n_in,
                              void* d_out, int out_size) {
    const float* theta = (const float*)d_in[0];
    const float* T     = (const float*)d_in[1];
    const float* x     = (const float*)d_in[2];
    const float* a     = (const float*)d_in[3];
    const float* alpha = (const float*)d_in[4];
    const float* W     = (const float*)d_in[5];
    const float* bias  = (const float*)d_in[6];
    (void)in_sizes; (void)n_in; (void)out_size;

    xconv_kernel<<<128, 256>>>(x);
    cudaFuncSetAttribute(ggd_kernel, cudaFuncAttributeMaxDynamicSharedMemorySize,
                         SMEM_WORDS * 4);
    ggd_kernel<<<NN / BM, TPB, SMEM_WORDS * 4>>>(theta, T, a, alpha, W, bias,
                                                 (float*)d_out);
}

// round 16
// speedup vs baseline: 1.3011x; 1.0089x over previous
#include <cuda_runtime.h>
#include <cstdint>

// GeneralizedGraphDiffusion: out = prelu((sum_k theta_k*T_k * a) @ x) @ W^T + b
// N=8192, D=128, K=4.
// R16: R15 (64-K iters, 4-slot ring, a reg-staged, x pre-converted to tf32)
// with BM 64->56, grid 147 -> all 148 SMs. Rows 56..63 clamped duplicates.

#define NN 8192
#define DDIM 128
#define BM 56
#define NT 128                  // iterations of 64 K-columns
#define TPB 256

// smem float offsets (64-row tile layout kept; rows 56..63 are dup rows)
#define SLOT 12544              // T 8192 + X 4352
#define XOFF 8192
#define XSTR 136
#define AOFF 50176              // 4*SLOT ; A = [2][64][36] = 4608
#define SMEM_WORDS 54784        // 219136 bytes
#define HS_STRIDE 132

__device__ float g_xconv[NN * DDIM];   // tf32-rounded x

extern __shared__ float sm[];

__device__ __forceinline__ uint32_t tf32r(float f) {
    uint32_t r;
    asm("cvt.rna.tf32.f32 %0, %1;" : "=r"(r) : "f"(f));
    return r;
}
__device__ __forceinline__ void mma8(float* c, uint32_t a0, uint32_t a1,
                                     uint32_t a2, uint32_t a3,
                                     uint32_t b0, uint32_t b1) {
    asm volatile(
        "mma.sync.aligned.m16n8k8.row.col.f32.tf32.tf32.f32 "
        "{%0,%1,%2,%3}, {%4,%5,%6,%7}, {%8,%9}, {%0,%1,%2,%3};"
        : "+f"(c[0]), "+f"(c[1]), "+f"(c[2]), "+f"(c[3])
        : "r"(a0), "r"(a1), "r"(a2), "r"(a3), "r"(b0), "r"(b1));
}
__device__ __forceinline__ void cpa16(uint32_t dst, const float* src) {
    asm volatile("cp.async.cg.shared.global [%0], [%1], 16;" :: "r"(dst), "l"(src));
}
#define CP_COMMIT() asm volatile("cp.async.commit_group;" ::: "memory")
#define CP_WAIT0()  asm volatile("cp.async.wait_group 0;" ::: "memory")
#define STS128(ad, x, y, z, w) \
    asm volatile("st.shared.v4.b32 [%0], {%1,%2,%3,%4};" :: \
        "r"(ad), "r"(x), "r"(y), "r"(z), "r"(w) : "memory")

// ---- pre-pass: convert x to tf32 once ----
__global__ __launch_bounds__(256, 1)
void xconv_kernel(const float* __restrict__ x) {
    int idx = blockIdx.x * 256 + threadIdx.x;   // float4 index
#pragma unroll
    for (int q = 0; q < 8; q++) {
        int e = idx + q * 32768;
        float4 v = *(const float4*)(x + (size_t)e * 4);
        uint4 o;
        o.x = tf32r(v.x); o.y = tf32r(v.y); o.z = tf32r(v.z); o.w = tf32r(v.w);
        *(uint4*)(g_xconv + (size_t)e * 4) = o;
    }
}

__global__ __launch_bounds__(TPB, 1)
void ggd_kernel(const float* __restrict__ theta, const float* __restrict__ T,
                const float* __restrict__ a,
                const float* __restrict__ alpha, const float* __restrict__ W,
                const float* __restrict__ bias, float* __restrict__ out) {
    const int tid = threadIdx.x;
    const int lane = tid & 31, wid = tid >> 5;
    const int g = lane >> 2, tig = lane & 3;
    const int wr = wid & 1, wc = wid >> 1;
    const int i0 = blockIdx.x * BM;
    const size_t slice = (size_t)NN * NN;

    uint32_t sbase;
    asm("{ .reg .u64 t; cvta.to.shared.u64 t, %1; cvt.u32.u64 %0, t; }"
        : "=r"(sbase) : "l"(sm));

    // ---- cp.async precompute; T rows >= BM clamp to BM-1 (dup rows) ----
    const float* srcT[8]; uint32_t dstT[8];
#pragma unroll
    for (int q = 0; q < 8; q++) {
        int c = tid + q * 256;
        int k = c >> 9, rem = c & 511, r = rem >> 3, cc = (rem & 7) * 4;
        int rr = r < BM ? r : BM - 1;
        int row = i0 + rr; if (row > NN - 1) row = NN - 1;
        srcT[q] = T + (size_t)k * slice + (size_t)row * NN + cc;
        dstT[q] = (uint32_t)c * 16;
    }
    const float* srcX[4]; uint32_t dstX[4];
#pragma unroll
    for (int q = 0; q < 4; q++) {
        int c = tid + q * 256;
        int row = c >> 5, cc = (c & 31) * 4;
        srcX[q] = g_xconv + (size_t)row * DDIM + cc;
        dstX[q] = (uint32_t)(XOFF + row * XSTR + cc) * 4;
    }

#define ISSUE(J0, STG) do {                                                    \
    uint32_t _sb = sbase + (uint32_t)((STG) * SLOT) * 4;                       \
    _Pragma("unroll") for (int _q = 0; _q < 8; _q++)                           \
        cpa16(_sb + dstT[_q], srcT[_q] + (J0));                                \
    _Pragma("unroll") for (int _q = 0; _q < 4; _q++)                           \
        cpa16(_sb + dstX[_q], srcX[_q] + (size_t)(J0) * DDIM);                 \
} while (0)

    // ---- 'a' register staging with row clamps ----
    int ra0 = tid >> 3;                            // 0..31 (< BM)
    int rowa0 = i0 + ra0; if (rowa0 > NN - 1) rowa0 = NN - 1;
    int ra1 = 32 + (tid >> 3); if (ra1 > BM - 1) ra1 = BM - 1;
    int rowa1 = i0 + ra1; if (rowa1 > NN - 1) rowa1 = NN - 1;
    const size_t rbA0 = (size_t)rowa0 * NN + (tid & 7) * 4;
    const size_t rbA1 = (size_t)rowa1 * NN + (tid & 7) * 4;
    float4 pa[4];   // [half][qq]

#define LOADR_A(J0) do {                                                       \
    pa[0] = *(const float4*)(a + rbA0 + (J0));                                 \
    pa[1] = *(const float4*)(a + rbA1 + (J0));                                 \
    pa[2] = *(const float4*)(a + rbA0 + (J0) + 32);                            \
    pa[3] = *(const float4*)(a + rbA1 + (J0) + 32);                            \
} while (0)

    const float th0 = __ldg(theta), th1 = __ldg(theta + 1),
                th2 = __ldg(theta + 2), th3 = __ldg(theta + 3);

    float acc[2][4][4];
#pragma unroll
    for (int mi = 0; mi < 2; mi++)
#pragma unroll
        for (int nf = 0; nf < 4; nf++)
#pragma unroll
            for (int e = 0; e < 4; e++) acc[mi][nf][e] = 0.f;

    ISSUE(0, 0);
    ISSUE(32, 1);
    CP_COMMIT();
    LOADR_A(0);

    for (int t = 0; t < NT; t++) {
        CP_WAIT0();
        __syncthreads();

        const int s0 = (2 * t) & 3;
        if (t + 1 < NT) {
            ISSUE((t + 1) * 64,      (2 * t + 2) & 3);
            ISSUE((t + 1) * 64 + 32, (2 * t + 3) & 3);
            CP_COMMIT();
        }

        // ---- build A only ----
#pragma unroll
        for (int h = 0; h < 2; h++) {
            const float* traw = sm + ((s0 + h) & 3) * SLOT;
            uint32_t Abad = sbase + (uint32_t)(AOFF + h * 2304) * 4;
#pragma unroll
            for (int qq = 0; qq < 2; qq++) {
                int idx = tid + qq * 256;
                int row = idx >> 3, c4 = (idx & 7) * 4;
                float4 t0 = *(const float4*)(traw + row * 32 + c4);
                float4 t1 = *(const float4*)(traw + 2048 + row * 32 + c4);
                float4 t2 = *(const float4*)(traw + 4096 + row * 32 + c4);
                float4 t3 = *(const float4*)(traw + 6144 + row * 32 + c4);
                float4 av = pa[h * 2 + qq];
                uint32_t qx = tf32r((th0*t0.x + th1*t1.x + th2*t2.x + th3*t3.x) * av.x);
                uint32_t qy = tf32r((th0*t0.y + th1*t1.y + th2*t2.y + th3*t3.y) * av.y);
                uint32_t qz = tf32r((th0*t0.z + th1*t1.z + th2*t2.z + th3*t3.z) * av.z);
                uint32_t qw = tf32r((th0*t0.w + th1*t1.w + th2*t2.w + th3*t3.w) * av.w);
                STS128(Abad + (uint32_t)(row * 36 + c4) * 4, qx, qy, qz, qw);
            }
        }
        __syncthreads();

        if (t + 1 < NT) LOADR_A((t + 1) * 64);

        // ---- mma both halves ----
#pragma unroll
        for (int h = 0; h < 2; h++) {
            const uint32_t* As = (const uint32_t*)(sm + AOFF + h * 2304);
            const uint32_t* Xs = (const uint32_t*)(sm + ((s0 + h) & 3) * SLOT + XOFF);
#pragma unroll
            for (int ks = 0; ks < 4; ks++) {
                uint32_t af[2][4];
#pragma unroll
                for (int mi = 0; mi < 2; mi++) {
                    const uint32_t* ap = As + (wr*32 + mi*16 + g) * 36 + ks*8 + tig;
                    af[mi][0] = ap[0];
                    af[mi][1] = ap[8 * 36];
                    af[mi][2] = ap[4];
                    af[mi][3] = ap[8 * 36 + 4];
                }
#pragma unroll
                for (int nfl = 0; nfl < 4; nfl++) {
                    const int n = (wc*4 + nfl)*8 + g;
                    uint32_t b0 = Xs[(ks*8 + tig)     * XSTR + n];
                    uint32_t b1 = Xs[(ks*8 + tig + 4) * XSTR + n];
#pragma unroll
                    for (int mi = 0; mi < 2; mi++)
                        mma8(acc[mi][nfl], af[mi][0], af[mi][1], af[mi][2], af[mi][3],
                             b0, b1);
                }
            }
        }
    }

    // ---- epilogue: acc -> hs, prelu + projection ----
    __syncthreads();
    float* hs = sm;   // [64][HS_STRIDE]
#pragma unroll
    for (int mi = 0; mi < 2; mi++)
#pragma unroll
        for (int nfl = 0; nfl < 4; nfl++) {
            const int col = (wc*4 + nfl)*8 + tig*2;
            const int r0 = wr*32 + mi*16 + g;
            *(float2*)(hs + r0 * HS_STRIDE + col) =
                make_float2(acc[mi][nfl][0], acc[mi][nfl][1]);
            *(float2*)(hs + (r0 + 8) * HS_STRIDE + col) =
                make_float2(acc[mi][nfl][2], acc[mi][nfl][3]);
        }
    __syncthreads();

    const int tx = tid & 15, ty = tid >> 4;
    const int tx8 = tx * 8, ty4 = ty * 4;
    float oa[4][8];
#pragma unroll
    for (int m = 0; m < 4; m++)
#pragma unroll
        for (int u = 0; u < 8; u++) oa[m][u] = 0.f;

    for (int c4 = 0; c4 < 32; c4++) {
        float4 al = __ldg((const float4*)(alpha + c4 * 4));
        float4 wv[8];
#pragma unroll
        for (int u = 0; u < 8; u++)
            wv[u] = __ldg((const float4*)(W + (size_t)(tx8 + u) * DDIM + c4 * 4));
#pragma unroll
        for (int m = 0; m < 4; m++) {
            float4 hv = *(const float4*)(hs + (ty4 + m) * HS_STRIDE + c4 * 4);
            hv.x = hv.x > 0.f ? hv.x : al.x * hv.x;
            hv.y = hv.y > 0.f ? hv.y : al.y * hv.y;
            hv.z = hv.z > 0.f ? hv.z : al.z * hv.z;
            hv.w = hv.w > 0.f ? hv.w : al.w * hv.w;
#pragma unroll
            for (int u = 0; u < 8; u++)
                oa[m][u] += hv.x * wv[u].x + hv.y * wv[u].y +
                            hv.z * wv[u].z + hv.w * wv[u].w;
        }
    }
    float4 b0 = __ldg((const float4*)(bias + tx8));
    float4 b1 = __ldg((const float4*)(bias + tx8 + 4));
#pragma unroll
    for (int m = 0; m < 4; m++) {
        int r = ty4 + m;
        int grow = i0 + r;
        if (r < BM && grow < NN) {
            size_t go = (size_t)grow * DDIM;
            *(float4*)(out + go + tx8) =
                make_float4(oa[m][0] + b0.x, oa[m][1] + b0.y,
                            oa[m][2] + b0.z, oa[m][3] + b0.w);
            *(float4*)(out + go + tx8 + 4) =
                make_float4(oa[m][4] + b1.x, oa[m][5] + b1.y,
                            oa[m][6] + b1.z, oa[m][7] + b1.w);
        }
    }
}

extern "C" void kernel_launch(void* const* d_in, const int* in_sizes, int n_in,
                              void* d_out, int out_size) {
    const float* theta = (const float*)d_in[0];
    const float* T     = (const float*)d_in[1];
    const float* x     = (const float*)d_in[2];
    const float* a     = (const float*)d_in[3];
    const float* alpha = (const float*)d_in[4];
    const float* W     = (const float*)d_in[5];
    const float* bias  = (const float*)d_in[6];
    (void)in_sizes; (void)n_in; (void)out_size;

    xconv_kernel<<<128, 256>>>(x);
    cudaFuncSetAttribute(ggd_kernel, cudaFuncAttributeMaxDynamicSharedMemorySize,
                         SMEM_WORDS * 4);
    ggd_kernel<<<(NN + BM - 1) / BM, TPB, SMEM_WORDS * 4>>>(theta, T, a, alpha,
                                                            W, bias, (float*)d_out);
}